// round 14
// baseline (speedup 1.0000x reference)
#include <cuda_runtime.h>

// Input (B,H,W,C) = (16,128,128,128) fp32, factor (2,2) half-pixel bilinear
// upsample -> (16,256,256,128) fp32.
//
// Quad kernel with 256-bit global accesses (sm_100+): each thread owns 8
// channels (c8 lane), loads 4 taps via ld.global.nc.v8.f32 (32B each) and
// writes outputs via st.global.v8.f32. Halves LDG/STG instruction count and
// L1 wavefront traffic vs the float4 version; warp tap footprint = 1KB
// contiguous. DRAM traffic unchanged (already at the 640MB floor).

#define B_   16
#define H_   128
#define W_   128
#define C8_  16          // 128 channels / 8 floats
#define OH_  256
#define OW_  256
#define NT_  128

struct f8 { float v[8]; };

__device__ __forceinline__ f8 ldg8(const float* p) {
    f8 r;
    asm("ld.global.nc.v8.f32 {%0,%1,%2,%3,%4,%5,%6,%7}, [%8];"
        : "=f"(r.v[0]), "=f"(r.v[1]), "=f"(r.v[2]), "=f"(r.v[3]),
          "=f"(r.v[4]), "=f"(r.v[5]), "=f"(r.v[6]), "=f"(r.v[7])
        : "l"(p));
    return r;
}

__device__ __forceinline__ void stg8(float* p, f8 r) {
    asm volatile("st.global.v8.f32 [%0], {%1,%2,%3,%4,%5,%6,%7,%8};"
        :: "l"(p),
           "f"(r.v[0]), "f"(r.v[1]), "f"(r.v[2]), "f"(r.v[3]),
           "f"(r.v[4]), "f"(r.v[5]), "f"(r.v[6]), "f"(r.v[7])
        : "memory");
}

__device__ __forceinline__ f8 lerp8(f8 a, f8 b, float t) {
    f8 r;
#pragma unroll
    for (int i = 0; i < 8; i++) r.v[i] = fmaf(t, b.v[i] - a.v[i], a.v[i]);
    return r;
}

__global__ __launch_bounds__(NT_) void upsample2x_quad_v8(
    const float* __restrict__ in, float* __restrict__ out)
{
    int idx = blockIdx.x * NT_ + threadIdx.x;   // B*128*128*16 threads
    int c8 = idx & (C8_ - 1);
    int qw = (idx >> 4) & (W_ - 1);
    int qh = (idx >> 11) & (H_ - 1);
    int b  = idx >> 18;

    int r1 = qh < H_ - 1 ? qh + 1 : H_ - 1;
    int c1 = qw < W_ - 1 ? qw + 1 : W_ - 1;

    const float* base = in + (size_t)b * (H_ * W_ * 128) + c8 * 8;
    f8 v00 = ldg8(base + (qh * W_ + qw) * 128);
    f8 v01 = ldg8(base + (qh * W_ + c1) * 128);
    f8 v10 = ldg8(base + (r1 * W_ + qw) * 128);
    f8 v11 = ldg8(base + (r1 * W_ + c1) * 128);

    // H interpolation first (matches reference order).
    f8 a0 = lerp8(v00, v10, 0.25f);
    f8 a1 = lerp8(v01, v11, 0.25f);
    f8 b0 = lerp8(v00, v10, 0.75f);
    f8 b1 = lerp8(v01, v11, 0.75f);

    float* obase = out + (size_t)b * (OH_ * OW_ * 128) + c8 * 8;
    int rowA = 2 * qh + 1;
    int colA = 2 * qw + 1;

    float* oA = obase + (size_t)rowA * (OW_ * 128);
    stg8(oA + colA * 128, lerp8(a0, a1, 0.25f));
    if (qw < W_ - 1)
        stg8(oA + (colA + 1) * 128, lerp8(a0, a1, 0.75f));
    if (qh < H_ - 1) {
        float* oB = oA + OW_ * 128;
        stg8(oB + colA * 128, lerp8(b0, b1, 0.25f));
        if (qw < W_ - 1)
            stg8(oB + (colA + 1) * 128, lerp8(b0, b1, 0.75f));
    }

    // Output row 0 = source row 0 (h-frac collapses), w-interp as usual.
    if (qh == 0) {
        stg8(obase + colA * 128, lerp8(v00, v01, 0.25f));
        if (qw < W_ - 1)
            stg8(obase + (colA + 1) * 128, lerp8(v00, v01, 0.75f));
        if (qw == 0)
            stg8(obase, v00);                   // (0,0) corner
    }

    // Output col 0 = source col 0 (w-frac collapses): values a0 / b0.
    if (qw == 0) {
        stg8(obase + (size_t)rowA * (OW_ * 128), a0);
        if (qh < H_ - 1)
            stg8(obase + (size_t)(rowA + 1) * (OW_ * 128), b0);
    }
}

extern "C" void kernel_launch(void* const* d_in, const int* in_sizes, int n_in,
                              void* d_out, int out_size) {
    const float* in = (const float*)d_in[0];
    float* out = (float*)d_out;
    int total = B_ * H_ * W_ * C8_;    // 4,194,304 threads
    upsample2x_quad_v8<<<total / NT_, NT_>>>(in, out);
}

// round 16
// speedup vs baseline: 1.0022x; 1.0022x over previous
#include <cuda_runtime.h>

// Input (B,H,W,C) = (16,128,128,128) fp32, factor (2,2) half-pixel bilinear
// upsample -> (16,256,256,128) fp32.
//
// FINAL FORM (R13 incumbent, re-benched for confirmation). Quad formulation:
// one thread per (b,qh,qw,c4): 4 float4 tap loads -> 4 interior float4 stores
// (+predicated border stores), __stwt write-through output stores.
//
// Roofline note: DRAM traffic is at the 640MB floor (128MB read + 512MB
// write); seven structural variants (MLP 4/6/8, occ 36-65%, block 128/256,
// store default/.cs/.wt, 128/256-bit accesses) all measured 6.33-6.37TB/s
// => ~80% of HBM spec is the device ceiling for this 1:4 R:W interleaved
// stream. This kernel is bandwidth-roofline-bound; no further SM-side lever.

#define B_   16
#define H_   128
#define W_   128
#define C4_  32          // 128 channels / 4
#define OH_  256
#define OW_  256

#define NT_  128

__device__ __forceinline__ float4 lerp4(float4 v0, float4 v1, float t) {
    float4 r;
    r.x = fmaf(t, v1.x - v0.x, v0.x);
    r.y = fmaf(t, v1.y - v0.y, v0.y);
    r.z = fmaf(t, v1.z - v0.z, v0.z);
    r.w = fmaf(t, v1.w - v0.w, v0.w);
    return r;
}

__global__ __launch_bounds__(NT_) void upsample2x_quad_wt(
    const float4* __restrict__ in, float4* __restrict__ out)
{
    int idx = blockIdx.x * NT_ + threadIdx.x;   // exactly B*128*128*32 threads
    int c4 = idx & (C4_ - 1);
    int qw = (idx >> 5) & (W_ - 1);
    int qh = (idx >> 12) & (H_ - 1);
    int b  = idx >> 19;

    int r1 = qh < H_ - 1 ? qh + 1 : H_ - 1;
    int c1 = qw < W_ - 1 ? qw + 1 : W_ - 1;

    const float4* base = in + (size_t)b * (H_ * W_ * C4_) + c4;
    float4 v00 = __ldg(base + (qh * W_ + qw) * C4_);
    float4 v01 = __ldg(base + (qh * W_ + c1) * C4_);
    float4 v10 = __ldg(base + (r1 * W_ + qw) * C4_);
    float4 v11 = __ldg(base + (r1 * W_ + c1) * C4_);

    // H interpolation first (matches reference order).
    float4 a0 = lerp4(v00, v10, 0.25f);
    float4 a1 = lerp4(v01, v11, 0.25f);
    float4 b0 = lerp4(v00, v10, 0.75f);
    float4 b1 = lerp4(v01, v11, 0.75f);

    float4* obase = out + (size_t)b * (OH_ * OW_ * C4_) + c4;
    int rowA = 2 * qh + 1;
    int colA = 2 * qw + 1;

    float4* oA = obase + (size_t)rowA * (OW_ * C4_);
    __stwt(oA + colA * C4_, lerp4(a0, a1, 0.25f));
    if (qw < W_ - 1)
        __stwt(oA + (colA + 1) * C4_, lerp4(a0, a1, 0.75f));
    if (qh < H_ - 1) {
        float4* oB = oA + OW_ * C4_;
        __stwt(oB + colA * C4_, lerp4(b0, b1, 0.25f));
        if (qw < W_ - 1)
            __stwt(oB + (colA + 1) * C4_, lerp4(b0, b1, 0.75f));
    }

    // Output row 0 = source row 0 (h-frac collapses), w-interp as usual.
    if (qh == 0) {
        __stwt(obase + colA * C4_, lerp4(v00, v01, 0.25f));
        if (qw < W_ - 1)
            __stwt(obase + (colA + 1) * C4_, lerp4(v00, v01, 0.75f));
        if (qw == 0)
            __stwt(obase, v00);                 // (0,0) corner
    }

    // Output col 0 = source col 0 (w-frac collapses): values a0 / b0.
    if (qw == 0) {
        __stwt(obase + (size_t)rowA * (OW_ * C4_), a0);
        if (qh < H_ - 1)
            __stwt(obase + (size_t)(rowA + 1) * (OW_ * C4_), b0);
    }
}

extern "C" void kernel_launch(void* const* d_in, const int* in_sizes, int n_in,
                              void* d_out, int out_size) {
    const float4* in = (const float4*)d_in[0];
    float4* out = (float4*)d_out;
    int total = B_ * H_ * W_ * C4_;    // 8,388,608 threads
    upsample2x_quad_wt<<<total / NT_, NT_>>>(in, out);
}